// round 8
// baseline (speedup 1.0000x reference)
#include <cuda_runtime.h>
#include <cuda_fp16.h>
#include <cstdint>

// ============================================================================
// IndRNN on GB300 — prep (x->fp16, W^T->fp16) + FUSED GEMM/scan kernel.
//   Mainloop: pure cp.async (A and B fp16), 3-stage pipeline over a global
//   chunk index spanning all 4 t-tiles; HMMA m16n8k16 fp32-accum.
//   Epilogue per tile: two half-tile dump+scan phases (64 rows each),
//   scan h carried in registers, results STG'd directly (coalesced).
// Shapes: B=64, T=512, D(K)=256, U(N)=512, M=B*T=32768
// rel_err ~ 2.4e-4 (fp16 single-pass, identical rounding to R5-R7).
// ============================================================================

#define U_DIM 512
#define K_DIM 256
#define T_DIM 512
#define M_DIM 32768
#define MT 128
#define NT 128
#define KC 32
#define ROWB 80                        // 5*16: conflict-free ldmatrix
#define TSTG (128 * ROWB)              // one operand tile stage: 10240 B
#define STG_B (2 * TSTG)               // A + B per stage: 20480 B
#define NSTAGE 3
#define STAGES_BYTES (NSTAGE * STG_B)  // 61440 B
#define SCROW 132
#define SCBYTES (64 * SCROW * 4)       // 33792 B (half tile)
#define SMEM_BYTES (STAGES_BYTES + SCBYTES)  // 95232 B -> occ 2

__device__ __half g_Wt[U_DIM * K_DIM];   // W^T [N][K] fp16
__device__ __half g_Xh[M_DIM * K_DIM];   // x   [M][K] fp16

// ---------------------------------------------------------------- helpers
__device__ __forceinline__ uint32_t smem_u32(const void* p) {
    uint32_t a;
    asm("{ .reg .u64 t; cvta.to.shared.u64 t, %1; cvt.u32.u64 %0, t; }"
        : "=r"(a) : "l"(p));
    return a;
}
__device__ __forceinline__ void ldsm_x4(uint32_t* r, uint32_t addr) {
    asm volatile("ldmatrix.sync.aligned.m8n8.x4.shared.b16 {%0,%1,%2,%3}, [%4];"
                 : "=r"(r[0]), "=r"(r[1]), "=r"(r[2]), "=r"(r[3]) : "r"(addr));
}
__device__ __forceinline__ void mma_f16(float* c, const uint32_t* a,
                                        uint32_t b0, uint32_t b1) {
    asm volatile(
        "mma.sync.aligned.m16n8k16.row.col.f32.f16.f16.f32 "
        "{%0,%1,%2,%3}, {%4,%5,%6,%7}, {%8,%9}, {%0,%1,%2,%3};"
        : "+f"(c[0]), "+f"(c[1]), "+f"(c[2]), "+f"(c[3])
        : "r"(a[0]), "r"(a[1]), "r"(a[2]), "r"(a[3]), "r"(b0), "r"(b1));
}
__device__ __forceinline__ void cp_async16(uint32_t dst, const void* src) {
    asm volatile("cp.async.cg.shared.global [%0], [%1], 16;"
                 :: "r"(dst), "l"(src) : "memory");
}
#define CP_COMMIT() asm volatile("cp.async.commit_group;" ::: "memory")
#define CP_WAIT1()  asm volatile("cp.async.wait_group 1;" ::: "memory")

__device__ __forceinline__ uint32_t pack_h2(__half a, __half b) {
    __half2 p(a, b);
    return *reinterpret_cast<uint32_t*>(&p);
}

// ---------------------------------------------------------------- prep kernel
// blocks [0,128): W transpose tiles (16 x 8 of 32x32). blocks [128,1152): x cvt.
__global__ __launch_bounds__(256)
void prep_kernel(const float* __restrict__ W, const float* __restrict__ X) {
    if (blockIdx.x < 128) {
        __shared__ float tile[32][33];
        const int bw = blockIdx.x;
        const int n0 = (bw & 15) * 32, k0 = (bw >> 4) * 32;
        const int tx = threadIdx.x & 31, ty = threadIdx.x >> 5;   // 32 x 8
        #pragma unroll
        for (int i = 0; i < 32; i += 8)
            tile[ty + i][tx] = W[(size_t)(k0 + ty + i) * U_DIM + n0 + tx];
        __syncthreads();
        #pragma unroll
        for (int i = 0; i < 32; i += 8)
            g_Wt[(size_t)(n0 + ty + i) * K_DIM + k0 + tx] =
                __float2half_rn(tile[tx][ty + i]);
    } else {
        // 1024 blocks, 256 thr, 8 float4 each: 1024*256*8*4 = 8.4M floats
        const int bx = blockIdx.x - 128;
        #pragma unroll
        for (int i = 0; i < 8; i++) {
            size_t idx = (size_t)bx * 2048 + i * 256 + threadIdx.x;  // float4 idx
            float4 v = reinterpret_cast<const float4*>(X)[idx];
            uint2 o;
            o.x = pack_h2(__float2half_rn(v.x), __float2half_rn(v.y));
            o.y = pack_h2(__float2half_rn(v.z), __float2half_rn(v.w));
            *reinterpret_cast<uint2*>(g_Xh + idx * 4) = o;
        }
    }
}

// ---------------------------------------------------------------- fused kernel
// 256 threads = 8 warps: wm = wid&3 (m), wn = wid>>2 (n). Warp tile 32x64.
__global__ __launch_bounds__(256, 2)
void indrnn_fused_kernel(const float* __restrict__ bias,  // [N]
                         const float* __restrict__ h0g,   // [B, U]
                         const float* __restrict__ ug,    // [U]
                         float* __restrict__ C)           // out [M, U_DIM]
{
    extern __shared__ char smem[];
    const uint32_t sb = smem_u32(smem);                             // stages
    float* const scf = reinterpret_cast<float*>(smem + STAGES_BYTES); // scan buf

    const int tid  = threadIdx.x;
    const int lane = tid & 31;
    const int wid  = tid >> 5;
    const int wm   = wid & 3;
    const int wn   = wid >> 2;
    const int n0   = blockIdx.x * NT;
    const int b    = blockIdx.y;
    const int mB   = b * T_DIM;

    // scan state: thread tid<128 owns column n0+tid
    float h = 0.0f, uc = 0.0f;
    if (tid < 128) {
        uc = fminf(fmaxf(ug[n0 + tid], 0.0f), 1.0f);
        h  = h0g[(size_t)b * U_DIM + n0 + tid];
    }

    // cp.async mapping (identical for A and B): 512 x 16B, 2 per thread
    const int cRow[2] = { (0*256 + tid) >> 2, (1*256 + tid) >> 2 };
    const int cC16 = tid & 3;
    // ldmatrix lane offsets
    const uint32_t aOff = (uint32_t)((lane & 15) * ROWB + (lane >> 4) * 16);
    const uint32_t bOff = (uint32_t)(((lane & 7) + ((lane >> 4) & 1) * 8) * ROWB
                                     + ((lane >> 3) & 1) * 16);
    // dump fragment coords
    const int colBase = wn * 64 + (lane & 3) * 2;   // n_local
    const int rowBase = wm * 32 + (lane >> 2);      // t_local (0..127)

    // issue chunk ch (0..31): tile = ch>>3, k-slice = (ch&7)*KC
    auto issue_chunk = [&](int ch) {
        const uint32_t st = sb + (uint32_t)((ch % NSTAGE) * STG_B);
        const size_t mrow = (size_t)(mB + ((ch >> 3) << 7));
        const int kk = (ch & 7) * KC;
        #pragma unroll
        for (int i = 0; i < 2; i++) {
            cp_async16(st + (uint32_t)(cRow[i] * ROWB + cC16 * 16),
                       g_Xh + (mrow + cRow[i]) * K_DIM + kk + cC16 * 8);
            cp_async16(st + TSTG + (uint32_t)(cRow[i] * ROWB + cC16 * 16),
                       g_Wt + (size_t)(n0 + cRow[i]) * K_DIM + kk + cC16 * 8);
        }
        CP_COMMIT();
    };

    issue_chunk(0);
    issue_chunk(1);

    #pragma unroll 1
    for (int tc = 0; tc < T_DIM / MT; tc++) {
        const int m0 = mB + tc * MT;

        float acc[2][8][4];
        #pragma unroll
        for (int mt = 0; mt < 2; mt++)
            #pragma unroll
            for (int nt = 0; nt < 8; nt++)
                #pragma unroll
                for (int q = 0; q < 4; q++)
                    acc[mt][nt][q] = 0.0f;

        #pragma unroll 1
        for (int c = 0; c < 8; c++) {
            const int ch = tc * 8 + c;
            CP_WAIT1();
            __syncthreads();           // chunk ch resident; stage (ch+2)%3 free
            if (ch + 2 < 32) issue_chunk(ch + 2);

            const uint32_t uA = sb + (uint32_t)((ch % NSTAGE) * STG_B);
            const uint32_t uB = uA + TSTG;
            #pragma unroll
            for (int ks = 0; ks < 2; ks++) {
                const uint32_t kb = ks * 32;
                uint32_t ah[2][4];
                #pragma unroll
                for (int mt = 0; mt < 2; mt++)
                    ldsm_x4(ah[mt], uA + (uint32_t)((wm * 32 + mt * 16) * ROWB) + aOff + kb);
                #pragma unroll
                for (int np = 0; np < 4; np++) {
                    uint32_t bh[4];
                    ldsm_x4(bh, uB + (uint32_t)((wn * 64 + np * 16) * ROWB) + bOff + kb);
                    #pragma unroll
                    for (int mt = 0; mt < 2; mt++) {
                        mma_f16(acc[mt][np * 2 + 0], ah[mt], bh[0], bh[1]);
                        mma_f16(acc[mt][np * 2 + 1], ah[mt], bh[2], bh[3]);
                    }
                }
            }
        }

        // ---- two half-tile dump+scan phases (rows p*64 .. p*64+63) ----
        #pragma unroll 1
        for (int p = 0; p < 2; p++) {
            __syncthreads();   // prev phase's scan reads / prev tile done
            if ((wm >> 1) == p) {
                const int rloc = rowBase - p * 64;   // 0..63 for owning warps
                #pragma unroll
                for (int nt = 0; nt < 8; nt++) {
                    const int col = colBase + nt * 8;
                    float2 bv = *reinterpret_cast<const float2*>(bias + n0 + col);
                    #pragma unroll
                    for (int mt = 0; mt < 2; mt++) {
                        const int r = rloc + mt * 16;
                        float2 o0 = { acc[mt][nt][0] + bv.x, acc[mt][nt][1] + bv.y };
                        float2 o1 = { acc[mt][nt][2] + bv.x, acc[mt][nt][3] + bv.y };
                        *reinterpret_cast<float2*>(scf + (size_t)r * SCROW + col)       = o0;
                        *reinterpret_cast<float2*>(scf + (size_t)(r + 8) * SCROW + col) = o1;
                    }
                }
            }
            __syncthreads();
            if (tid < 128) {
                float* crow = C + (size_t)(m0 + p * 64) * U_DIM + n0 + tid;
                #pragma unroll
                for (int t = 0; t < 64; t += 8) {
                    float v[8];
                    #pragma unroll
                    for (int i = 0; i < 8; i++)
                        v[i] = scf[(size_t)(t + i) * SCROW + tid];
                    #pragma unroll
                    for (int i = 0; i < 8; i++) {
                        h = fmaxf(fmaf(h, uc, v[i]), 0.0f);
                        v[i] = h;
                    }
                    #pragma unroll
                    for (int i = 0; i < 8; i++)
                        crow[(size_t)(t + i) * U_DIM] = v[i];
                }
            }
        }
        __syncthreads();   // scan reads done before next tile's dump
    }
}

// ---------------------------------------------------------------- launch
extern "C" void kernel_launch(void* const* d_in, const int* in_sizes, int n_in,
                              void* d_out, int out_size)
{
    const float* x  = (const float*)d_in[0];  // [B,T,D]
    const float* h0 = (const float*)d_in[1];  // [B,U]
    const float* W  = (const float*)d_in[2];  // [D,U]
    const float* u  = (const float*)d_in[3];  // [U]
    const float* bb = (const float*)d_in[4];  // [U]
    float* out = (float*)d_out;               // [B,T,U]

    const int U = in_sizes[3];                // 512
    const int B = in_sizes[1] / U;            // 64

    // 1) prep: W^T -> fp16, x -> fp16
    prep_kernel<<<128 + 1024, 256>>>(W, x);

    // 2) fused GEMM + scan
    cudaFuncSetAttribute(indrnn_fused_kernel,
                         cudaFuncAttributeMaxDynamicSharedMemorySize, SMEM_BYTES);
    dim3 gg(U / NT, B);   // (4, 64) = 256 CTAs, single wave at occ 2
    indrnn_fused_kernel<<<gg, 256, SMEM_BYTES>>>(bb, h0, u, out);
}